// round 2
// baseline (speedup 1.0000x reference)
#include <cuda_runtime.h>

// LIF activation:
//   forget_t = step(1.0 - Vm)              (1 if Vm < 1.0, else 0 -> reset)
//   Vm       = relu(w_i * x_t + (1 - w_l) * Vm * forget_t)
//   spike_t  = step(Vm - 1.0)              (1 if Vm > 1.0)
// Serial over T (axis 1), independent over B*C = 65536 chains.
// x layout [B, T, C] with C contiguous -> thread per (b, c) is coalesced.

#define B_DIM 64
#define T_DIM 500
#define C_DIM 1024
#define UNROLL 10   // 500 % 10 == 0

__global__ __launch_bounds__(256, 2)
void lif_kernel(const float* __restrict__ x,
                const float* __restrict__ w_input_p,
                const float* __restrict__ w_leak_p,
                float* __restrict__ out)
{
    const int gid = blockIdx.x * blockDim.x + threadIdx.x;   // 0 .. B*C-1
    const int c = gid & (C_DIM - 1);
    const int b = gid >> 10;                                  // / C_DIM

    const float w_in = __ldg(w_input_p);
    const float one_minus_wl = 1.0f - __ldg(w_leak_p);

    // base index for (b, t=0, c)
    long long idx = (long long)b * (long long)(T_DIM * C_DIM) + c;

    const float* xp = x + idx;
    float* op = out + idx;

    float Vm = 0.0f;

    #pragma unroll 1
    for (int t0 = 0; t0 < T_DIM; t0 += UNROLL) {
        // Batch the loads first: independent of the Vm chain, so ptxas
        // front-batches UNROLL LDGs -> high MLP while the serial FMA chain runs.
        float xv[UNROLL];
        #pragma unroll
        for (int u = 0; u < UNROLL; u++) {
            xv[u] = __ldcs(xp + (size_t)u * C_DIM);   // streaming: no reuse
        }

        #pragma unroll
        for (int u = 0; u < UNROLL; u++) {
            // forget = step(1 - Vm): keep Vm only if it has NOT crossed threshold
            float kept = (Vm < 1.0f) ? Vm : 0.0f;
            Vm = fmaxf(fmaf(one_minus_wl, kept, w_in * xv[u]), 0.0f);
            float spike = (Vm > 1.0f) ? 1.0f : 0.0f;
            __stcs(op + (size_t)u * C_DIM, spike);    // streaming store
        }

        xp += (size_t)UNROLL * C_DIM;
        op += (size_t)UNROLL * C_DIM;
    }
}

extern "C" void kernel_launch(void* const* d_in, const int* in_sizes, int n_in,
                              void* d_out, int out_size)
{
    const float* x       = (const float*)d_in[0];
    const float* w_input = (const float*)d_in[1];
    const float* w_leak  = (const float*)d_in[2];
    float* out = (float*)d_out;

    const int total_threads = B_DIM * C_DIM;   // 65536
    const int tpb = 256;
    const int blocks = total_threads / tpb;    // 256

    lif_kernel<<<blocks, tpb>>>(x, w_input, w_leak, out);
}

// round 3
// speedup vs baseline: 1.0261x; 1.0261x over previous
#include <cuda_runtime.h>

// LIF activation, [B=64, T=500, C=1024] fp32 -> spikes same shape.
//   kept   = Vm < 1 ? Vm : 0          (reset on threshold crossing)
//   Vm     = max(w_in*x + (1-w_l)*kept, 0)
//   spike  = Vm > 1 ? 1 : 0
// Serial over T, independent over B*C chains. float2 per thread (2 chains),
// double-buffered register prefetch so DRAM latency overlaps the serial chain.

#define B_DIM 64
#define T_DIM 500
#define C_DIM 1024
#define CH2   (C_DIM / 2)          // 512 float2 per (b, t) row
#define UNROLL 10                  // timesteps per batch; 500 % 10 == 0
#define NB (T_DIM / UNROLL)        // 50 batches (even -> unroll-by-2 works)

__global__ __launch_bounds__(64, 8)
void lif_kernel(const float* __restrict__ x,
                const float* __restrict__ w_input_p,
                const float* __restrict__ w_leak_p,
                float* __restrict__ out)
{
    const int gid = blockIdx.x * blockDim.x + threadIdx.x;   // 0 .. B*CH2-1
    const int c2 = gid & (CH2 - 1);
    const int b  = gid >> 9;                                  // / CH2

    const float w_in = __ldg(w_input_p);
    const float omw  = 1.0f - __ldg(w_leak_p);

    const size_t base = (size_t)b * (size_t)(T_DIM * CH2) + c2;
    const float2* __restrict__ xp = (const float2*)x + base;
    float2* __restrict__ op = (float2*)out + base;

    float2 Vm = make_float2(0.0f, 0.0f);

    float2 bufA[UNROLL], bufB[UNROLL];

    // prime: batch 0 -> A
    #pragma unroll
    for (int u = 0; u < UNROLL; u++)
        bufA[u] = __ldcs(xp + (size_t)u * CH2);

    const float2* pf = xp + (size_t)UNROLL * CH2;   // prefetch cursor (batch 1)

    #pragma unroll 1
    for (int batch = 0; batch < NB; batch += 2) {
        // prefetch batch+1 -> B (batch+1 <= NB-1 always, since NB even)
        #pragma unroll
        for (int u = 0; u < UNROLL; u++)
            bufB[u] = __ldcs(pf + (size_t)u * CH2);
        pf += (size_t)UNROLL * CH2;

        // compute batch (from A)
        #pragma unroll
        for (int u = 0; u < UNROLL; u++) {
            float kx = (Vm.x < 1.0f) ? Vm.x : 0.0f;
            float ky = (Vm.y < 1.0f) ? Vm.y : 0.0f;
            Vm.x = fmaxf(fmaf(omw, kx, w_in * bufA[u].x), 0.0f);
            Vm.y = fmaxf(fmaf(omw, ky, w_in * bufA[u].y), 0.0f);
            float2 s;
            s.x = (Vm.x > 1.0f) ? 1.0f : 0.0f;
            s.y = (Vm.y > 1.0f) ? 1.0f : 0.0f;
            __stcs(op + (size_t)u * CH2, s);
        }
        op += (size_t)UNROLL * CH2;

        // prefetch batch+2 -> A (guard: last pair has none)
        if (batch + 2 < NB) {
            #pragma unroll
            for (int u = 0; u < UNROLL; u++)
                bufA[u] = __ldcs(pf + (size_t)u * CH2);
            pf += (size_t)UNROLL * CH2;
        }

        // compute batch+1 (from B)
        #pragma unroll
        for (int u = 0; u < UNROLL; u++) {
            float kx = (Vm.x < 1.0f) ? Vm.x : 0.0f;
            float ky = (Vm.y < 1.0f) ? Vm.y : 0.0f;
            Vm.x = fmaxf(fmaf(omw, kx, w_in * bufB[u].x), 0.0f);
            Vm.y = fmaxf(fmaf(omw, ky, w_in * bufB[u].y), 0.0f);
            float2 s;
            s.x = (Vm.x > 1.0f) ? 1.0f : 0.0f;
            s.y = (Vm.y > 1.0f) ? 1.0f : 0.0f;
            __stcs(op + (size_t)u * CH2, s);
        }
        op += (size_t)UNROLL * CH2;
    }
}

extern "C" void kernel_launch(void* const* d_in, const int* in_sizes, int n_in,
                              void* d_out, int out_size)
{
    const float* x       = (const float*)d_in[0];
    const float* w_input = (const float*)d_in[1];
    const float* w_leak  = (const float*)d_in[2];
    float* out = (float*)d_out;

    const int total_threads = B_DIM * CH2;     // 32768
    const int tpb = 64;
    const int blocks = total_threads / tpb;    // 512

    lif_kernel<<<blocks, tpb>>>(x, w_input, w_leak, out);
}